// round 10
// baseline (speedup 1.0000x reference)
#include <cuda_runtime.h>

// Weighted BCE loss, mean-reduced, single fused kernel.
// loss_i = (t_i==1) ? -log(o_i + eps) : -8 * log(1 - o_i + eps);  out = mean(loss)
// Static one-wave grid-stride; streaming (evict-first) loads; last-block finalize.

#define NEG_WEIGHT 8.0f
#define BCE_EPS    1e-7f

// Exactly one wave: 148 SMs x 8 resident blocks (256 thr, <=32 regs)
#define NBLOCKS  1184
#define NTHREADS 256

__device__ double       g_acc;    // zero-init; reset by last block each launch
__device__ unsigned int g_count;  // zero-init; reset by last block each launch

__device__ __forceinline__ float bce_elem(float o, int t) {
    // one log per element: x = t ? o : 1-o ; w = t ? 1 : 8
    float x = (t == 1) ? o : (1.0f - o);
    float w = (t == 1) ? 1.0f : NEG_WEIGHT;
    return w * (-__logf(x + BCE_EPS));
}

__device__ __forceinline__ float bce_quad(float4 o, int4 t) {
    // two independent chains to shorten FADD dependency
    float a = bce_elem(o.x, t.x) + bce_elem(o.z, t.z);
    float b = bce_elem(o.y, t.y) + bce_elem(o.w, t.w);
    return a + b;
}

__global__ void __launch_bounds__(NTHREADS)
bce_fused_kernel(const float4* __restrict__ out4,
                 const int4*   __restrict__ tgt4,
                 const float*  __restrict__ out_s,
                 const int*    __restrict__ tgt_s,
                 float* __restrict__ result,
                 int n4, int n)
{
    const int idx    = blockIdx.x * blockDim.x + threadIdx.x;
    const int stride = gridDim.x * blockDim.x;

    float acc0 = 0.0f, acc1 = 0.0f;

    // 2x unrolled grid-stride: 4 front-batched streaming LDG.128 per iteration
    int i = idx;
    for (; i + stride < n4; i += 2 * stride) {
        float4 o0 = __ldcs(&out4[i]);
        int4   t0 = __ldcs(&tgt4[i]);
        float4 o1 = __ldcs(&out4[i + stride]);
        int4   t1 = __ldcs(&tgt4[i + stride]);
        acc0 += bce_quad(o0, t0);
        acc1 += bce_quad(o1, t1);
    }
    if (i < n4) {
        float4 o0 = __ldcs(&out4[i]);
        int4   t0 = __ldcs(&tgt4[i]);
        acc0 += bce_quad(o0, t0);
    }

    float acc = acc0 + acc1;

    // scalar tail (n not divisible by 4)
    if (idx == 0) {
        for (int k = n4 * 4; k < n; k++)
            acc += bce_elem(out_s[k], tgt_s[k]);
    }

    // intra-block reduction: warp shuffle, then smem across warps
    #pragma unroll
    for (int off = 16; off > 0; off >>= 1)
        acc += __shfl_down_sync(0xffffffffu, acc, off);

    __shared__ float s_warp[NTHREADS / 32];
    if ((threadIdx.x & 31) == 0)
        s_warp[threadIdx.x >> 5] = acc;
    __syncthreads();

    if (threadIdx.x == 0) {
        float bsum = 0.0f;
        #pragma unroll
        for (int w = 0; w < NTHREADS / 32; w++)
            bsum += s_warp[w];

        // cross-block accumulation in double, last block finalizes
        atomicAdd(&g_acc, (double)bsum);
        __threadfence();
        unsigned int old = atomicAdd(&g_count, 1u);
        if (old == gridDim.x - 1) {
            double total = g_acc;
            result[0] = (float)(total / (double)n);
            // reset for next graph replay
            g_acc   = 0.0;
            g_count = 0u;
            __threadfence();
        }
    }
}

extern "C" void kernel_launch(void* const* d_in, const int* in_sizes, int n_in,
                              void* d_out, int out_size)
{
    const float* outputs = (const float*)d_in[0];
    const int*   targets = (const int*)d_in[1];
    float* out = (float*)d_out;

    int n  = in_sizes[0];
    int n4 = n >> 2;

    bce_fused_kernel<<<NBLOCKS, NTHREADS>>>(
        (const float4*)outputs, (const int4*)targets,
        outputs, targets, out, n4, n);
}

// round 11
// speedup vs baseline: 1.0115x; 1.0115x over previous
#include <cuda_runtime.h>

// Weighted BCE loss, mean-reduced, single fused kernel.
// loss_i = (t_i==1) ? -log(o_i + eps) : -8 * log(1 - o_i + eps);  out = mean(loss)
// Static one-wave grid-stride, 4x unroll (8 streaming LDG.128 in flight),
// last-block finalize.

#define NEG_WEIGHT 8.0f
#define BCE_EPS    1e-7f

// One wave at 6 blocks/SM (reg cap 40): 148 x 6 = 888
#define NBLOCKS  888
#define NTHREADS 256

__device__ double       g_acc;    // zero-init; reset by last block each launch
__device__ unsigned int g_count;  // zero-init; reset by last block each launch

__device__ __forceinline__ float bce_elem(float o, int t) {
    // one log per element: x = t ? o : 1-o ; w = t ? 1 : 8
    float x = (t == 1) ? o : (1.0f - o);
    float w = (t == 1) ? 1.0f : NEG_WEIGHT;
    return w * (-__logf(x + BCE_EPS));
}

__device__ __forceinline__ float bce_quad(float4 o, int4 t) {
    // two independent chains to shorten FADD dependency
    float a = bce_elem(o.x, t.x) + bce_elem(o.z, t.z);
    float b = bce_elem(o.y, t.y) + bce_elem(o.w, t.w);
    return a + b;
}

__global__ void __launch_bounds__(NTHREADS, 6)
bce_fused_kernel(const float4* __restrict__ out4,
                 const int4*   __restrict__ tgt4,
                 const float*  __restrict__ out_s,
                 const int*    __restrict__ tgt_s,
                 float* __restrict__ result,
                 int n4, int n)
{
    const int idx    = blockIdx.x * blockDim.x + threadIdx.x;
    const int stride = gridDim.x * blockDim.x;

    float acc0 = 0.0f, acc1 = 0.0f, acc2 = 0.0f, acc3 = 0.0f;

    // 4x unrolled grid-stride: 8 front-batched streaming LDG.128 per iteration
    int i = idx;
    for (; i + 3 * stride < n4; i += 4 * stride) {
        float4 o0 = __ldcs(&out4[i]);
        float4 o1 = __ldcs(&out4[i + stride]);
        float4 o2 = __ldcs(&out4[i + 2 * stride]);
        float4 o3 = __ldcs(&out4[i + 3 * stride]);
        int4   t0 = __ldcs(&tgt4[i]);
        int4   t1 = __ldcs(&tgt4[i + stride]);
        int4   t2 = __ldcs(&tgt4[i + 2 * stride]);
        int4   t3 = __ldcs(&tgt4[i + 3 * stride]);
        acc0 += bce_quad(o0, t0);
        acc1 += bce_quad(o1, t1);
        acc2 += bce_quad(o2, t2);
        acc3 += bce_quad(o3, t3);
    }
    for (; i < n4; i += stride) {
        float4 o0 = __ldcs(&out4[i]);
        int4   t0 = __ldcs(&tgt4[i]);
        acc0 += bce_quad(o0, t0);
    }

    float acc = (acc0 + acc1) + (acc2 + acc3);

    // scalar tail (n not divisible by 4)
    if (idx == 0) {
        for (int k = n4 * 4; k < n; k++)
            acc += bce_elem(out_s[k], tgt_s[k]);
    }

    // intra-block reduction: warp shuffle, then smem across warps
    #pragma unroll
    for (int off = 16; off > 0; off >>= 1)
        acc += __shfl_down_sync(0xffffffffu, acc, off);

    __shared__ float s_warp[NTHREADS / 32];
    if ((threadIdx.x & 31) == 0)
        s_warp[threadIdx.x >> 5] = acc;
    __syncthreads();

    if (threadIdx.x == 0) {
        float bsum = 0.0f;
        #pragma unroll
        for (int w = 0; w < NTHREADS / 32; w++)
            bsum += s_warp[w];

        // cross-block accumulation in double, last block finalizes
        atomicAdd(&g_acc, (double)bsum);
        __threadfence();
        unsigned int old = atomicAdd(&g_count, 1u);
        if (old == gridDim.x - 1) {
            double total = g_acc;
            result[0] = (float)(total / (double)n);
            // reset for next graph replay
            g_acc   = 0.0;
            g_count = 0u;
            __threadfence();
        }
    }
}

extern "C" void kernel_launch(void* const* d_in, const int* in_sizes, int n_in,
                              void* d_out, int out_size)
{
    const float* outputs = (const float*)d_in[0];
    const int*   targets = (const int*)d_in[1];
    float* out = (float*)d_out;

    int n  = in_sizes[0];
    int n4 = n >> 2;

    bce_fused_kernel<<<NBLOCKS, NTHREADS>>>(
        (const float4*)outputs, (const int4*)targets,
        outputs, targets, out, n4, n);
}